// round 12
// baseline (speedup 1.0000x reference)
#include <cuda_runtime.h>
#include <cuda_bf16.h>
#include <math.h>
#include <cstdint>

#define B_    2
#define SEQL  2048
#define DIM_  1024
#define NH_   16
#define HD_   64
#define HID_  2816
#define NTOK  (B_*SEQL)          // 4096
#define NQKV  (3*DIM_)           // 3072
#define N13   (2*HID_)           // 5632
#define NPATB 8192               // patches per batch (128*64)

// ---------------- scratch (device globals; no allocations allowed) ----------
__device__ float g_t[B_*512];
__device__ float g_kc[4*256];
__device__ float g_x1[NTOK*DIM_];
// bf16 activations
__device__ __nv_bfloat16 g_qkvb[NTOK*NQKV];
__device__ __nv_bfloat16 g_qb[NTOK*DIM_];
__device__ __nv_bfloat16 g_kb[NTOK*DIM_];
__device__ __nv_bfloat16 g_vb[NTOK*DIM_];
__device__ __nv_bfloat16 g_xmodb[NTOK*DIM_];
__device__ __nv_bfloat16 g_attnb[NTOK*DIM_];
__device__ __nv_bfloat16 g_x1mb[NTOK*DIM_];
__device__ __nv_bfloat16 g_hhb[NTOK*HID_];
__device__ __nv_bfloat16 g_hab[NTOK*DIM_];
__device__ __nv_bfloat16 g_hmb[NTOK*DIM_];
// modulate-as-GEMM scratch
__device__ __nv_bfloat16 g_kmat[4*256*256];        // [which][b][n][k]
__device__ __nv_bfloat16 g_xpat[NTOK*DIM_];        // patch-major input
// bf16 transposed weights [N][K]
__device__ __nv_bfloat16 g_wqkvt[NQKV*DIM_];
__device__ __nv_bfloat16 g_wot[DIM_*DIM_];
__device__ __nv_bfloat16 g_w13t[N13*DIM_];         // interleaved: row 2j=w1_j, 2j+1=w3_j
__device__ __nv_bfloat16 g_w2t[DIM_*HID_];

// ====================== mma.sync helpers (family-safe) =======================
__device__ __forceinline__ uint32_t smem_u32(const void* p) {
    uint32_t a;
    asm("{ .reg .u64 t; cvta.to.shared.u64 t, %1; cvt.u32.u64 %0, t; }" : "=r"(a) : "l"(p));
    return a;
}
__device__ __forceinline__ void ldsm_x4(uint32_t* r, uint32_t addr) {
    asm volatile("ldmatrix.sync.aligned.m8n8.x4.shared.b16 {%0,%1,%2,%3}, [%4];"
                 : "=r"(r[0]), "=r"(r[1]), "=r"(r[2]), "=r"(r[3]) : "r"(addr));
}
__device__ __forceinline__ void ldsm_x4t(uint32_t* r, uint32_t addr) {
    asm volatile("ldmatrix.sync.aligned.m8n8.x4.trans.shared.b16 {%0,%1,%2,%3}, [%4];"
                 : "=r"(r[0]), "=r"(r[1]), "=r"(r[2]), "=r"(r[3]) : "r"(addr));
}
__device__ __forceinline__ void mma16816(float* c, const uint32_t* a, const uint32_t* b) {
    asm volatile("mma.sync.aligned.m16n8k16.row.col.f32.bf16.bf16.f32 "
                 "{%0,%1,%2,%3}, {%4,%5,%6,%7}, {%8,%9}, {%0,%1,%2,%3};"
                 : "+f"(c[0]), "+f"(c[1]), "+f"(c[2]), "+f"(c[3])
                 : "r"(a[0]), "r"(a[1]), "r"(a[2]), "r"(a[3]), "r"(b[0]), "r"(b[1]));
}
__device__ __forceinline__ uint32_t packbf(float lo, float hi) {
    __nv_bfloat162 p = __floats2bfloat162_rn(lo, hi);
    return *(uint32_t*)&p;
}
#define CPASYNC16(saddr, gptr) \
    asm volatile("cp.async.cg.shared.global [%0], [%1], 16;" :: "r"(saddr), "l"(gptr))
#define CP_COMMIT() asm volatile("cp.async.commit_group;" ::: "memory")
#define CP_WAIT(n)  asm volatile("cp.async.wait_group %0;" :: "n"(n) : "memory")

// ============== cp.async 3-stage mma.sync GEMM, 256x128 CTA tile =============
#define SPAD   40
#define STG    3
#define ASTAGE (256*SPAD*2)
#define BSTAGE (128*SPAD*2)
#define STAGEB (ASTAGE+BSTAGE)
#define GEMM_SMEM (STG*STAGEB)

struct EpiBF16 {
    __nv_bfloat16* C; int N;
    __device__ __forceinline__ void store(int r0, int col, const float* a) const {
        *(uint32_t*)(C + (size_t)r0*N + col)     = packbf(a[0], a[1]);
        *(uint32_t*)(C + (size_t)(r0+8)*N + col) = packbf(a[2], a[3]);
    }
};
struct EpiSwiglu {
    __nv_bfloat16* out; const float* su; const float* sv;
    __device__ __forceinline__ void store(int r0, int col, const float* a) const {
        int j = col >> 1;
        float svj = sv[j] * 53.06599665f;
        float suj = su[j];
        float z0 = a[0]*svj, z1 = a[2]*svj;
        float h0 = z0 / (1.f + __expf(-z0)) * (a[1]*suj);
        float h1 = z1 / (1.f + __expf(-z1)) * (a[3]*suj);
        out[(size_t)r0*HID_ + j]     = __float2bfloat16(h0);
        out[(size_t)(r0+8)*HID_ + j] = __float2bfloat16(h1);
    }
};
struct EpiMod {
    __nv_bfloat16* Y;
    __device__ __forceinline__ void store(int p, int n, const float* a) const {
        int grow0 = ((p >> 6) << 4) + (n >> 4);
        int gcol  = ((p & 63) << 4) + (n & 15);
        int grow1 = (((p+8) >> 6) << 4) + (n >> 4);
        int gcol1 = (((p+8) & 63) << 4) + (n & 15);
        *(uint32_t*)(Y + (size_t)grow0*DIM_ + gcol)  = packbf(a[0], a[1]);
        *(uint32_t*)(Y + (size_t)grow1*DIM_ + gcol1) = packbf(a[2], a[3]);
    }
};

template<class Epi>
__device__ __forceinline__ void tgemm_core(const __nv_bfloat16* __restrict__ A,
                                           const __nv_bfloat16* __restrict__ Bt,
                                           int K, uint32_t sbase, const Epi& epi)
{
    int tid = threadIdx.x, lane = tid & 31, wid = tid >> 5;
    int wr = wid >> 1, wc = wid & 1;
    int row0 = blockIdx.y * 256, col0 = blockIdx.x * 128;

    int arow = tid >> 2, aseg = tid & 3;
    const __nv_bfloat16* Ag = A  + (size_t)(row0 + arow)*K + aseg*8;
    const __nv_bfloat16* Bg = Bt + (size_t)(col0 + arow)*K + aseg*8;
    uint32_t sAo = arow*(SPAD*2) + aseg*16;
    uint32_t sBo = ASTAGE + arow*(SPAD*2) + aseg*16;

    int NC = K >> 5;

    #pragma unroll
    for (int s = 0; s < STG-1; s++) {
        uint32_t st = sbase + s*STAGEB;
        const __nv_bfloat16* Ap = Ag + (size_t)s*32;
        const __nv_bfloat16* Bp = Bg + (size_t)s*32;
        #pragma unroll
        for (int i = 0; i < 4; i++)
            CPASYNC16(st + sAo + i*64*(SPAD*2), Ap + (size_t)i*64*K);
        #pragma unroll
        for (int i = 0; i < 2; i++)
            CPASYNC16(st + sBo + i*64*(SPAD*2), Bp + (size_t)i*64*K);
        CP_COMMIT();
    }

    float acc[4][8][4];
    #pragma unroll
    for (int i = 0; i < 4; i++)
        #pragma unroll
        for (int j = 0; j < 8; j++)
            #pragma unroll
            for (int q = 0; q < 4; q++) acc[i][j][q] = 0.f;

    int aq = lane >> 3, arw = lane & 7;
    int a_r = (aq & 1)*8 + arw;
    int a_kb = (aq >> 1)*16;
    int b_r2 = ((lane >> 4) << 3) + (lane & 7);
    int b_kb2 = ((lane >> 3) & 1)*16;

    int buf = 0;
    for (int c = 0; c < NC; c++) {
        CP_WAIT(STG-2);
        __syncthreads();

        if (c + STG-1 < NC) {
            int pb = buf - 1; if (pb < 0) pb += STG;
            uint32_t st = sbase + pb*STAGEB;
            const __nv_bfloat16* Ap = Ag + (size_t)(c+STG-1)*32;
            const __nv_bfloat16* Bp = Bg + (size_t)(c+STG-1)*32;
            #pragma unroll
            for (int i = 0; i < 4; i++)
                CPASYNC16(st + sAo + i*64*(SPAD*2), Ap + (size_t)i*64*K);
            #pragma unroll
            for (int i = 0; i < 2; i++)
                CPASYNC16(st + sBo + i*64*(SPAD*2), Bp + (size_t)i*64*K);
        }
        CP_COMMIT();

        uint32_t aBase = sbase + buf*STAGEB;
        uint32_t bBase = aBase + ASTAGE;
        #pragma unroll
        for (int ks = 0; ks < 2; ks++) {
            uint32_t afr[4][4], bfr[8][2];
            #pragma unroll
            for (int mt = 0; mt < 4; mt++)
                ldsm_x4(afr[mt], aBase + (wr*64 + mt*16 + a_r)*(SPAD*2) + ks*32 + a_kb);
            #pragma unroll
            for (int ntp = 0; ntp < 4; ntp++) {
                uint32_t b4[4];
                ldsm_x4(b4, bBase + (wc*64 + ntp*16 + b_r2)*(SPAD*2) + ks*32 + b_kb2);
                bfr[2*ntp][0]   = b4[0]; bfr[2*ntp][1]   = b4[1];
                bfr[2*ntp+1][0] = b4[2]; bfr[2*ntp+1][1] = b4[3];
            }
            #pragma unroll
            for (int mt = 0; mt < 4; mt++)
                #pragma unroll
                for (int nt = 0; nt < 8; nt++)
                    mma16816(acc[mt][nt], afr[mt], bfr[nt]);
        }
        __syncthreads();
        buf++; if (buf == STG) buf = 0;
    }

    int cr = lane >> 2, cc = (lane & 3)*2;
    #pragma unroll
    for (int mt = 0; mt < 4; mt++) {
        int r0 = row0 + wr*64 + mt*16 + cr;
        #pragma unroll
        for (int nt = 0; nt < 8; nt++)
            epi.store(r0, col0 + wc*64 + nt*8 + cc, acc[mt][nt]);
    }
}

template<class Epi>
__global__ __launch_bounds__(256) void tgemm_epi(const __nv_bfloat16* __restrict__ A,
                                                 const __nv_bfloat16* __restrict__ Bt,
                                                 int K, Epi epi)
{
    extern __shared__ char smemraw[];
    tgemm_core<Epi>(A, Bt, K, smem_u32(smemraw), epi);
}

__global__ __launch_bounds__(256) void tgemm_mod(const __nv_bfloat16* __restrict__ A,
                                                 const __nv_bfloat16* __restrict__ Bt,
                                                 __nv_bfloat16* __restrict__ Y)
{
    extern __shared__ char smemraw[];
    int z = blockIdx.z;
    EpiMod epi{ Y + (size_t)z*SEQL*DIM_ };
    tgemm_core<EpiMod>(A + (size_t)z*NPATB*256, Bt + (size_t)z*256*256,
                       256, smem_u32(smemraw), epi);
}

// -------- weight transpose + bf16 convert ------------------------------------
__global__ void wtrans_kernel(const float* __restrict__ W, __nv_bfloat16* __restrict__ Wt,
                              int K, int N, int rs, int ro)
{
    __shared__ float t[32][33];
    int tx = threadIdx.x, ty = threadIdx.y;
    int n = blockIdx.x*32 + tx;
    int k0 = blockIdx.y*32;
    #pragma unroll
    for (int j = 0; j < 32; j += 8)
        t[ty+j][tx] = W[(size_t)(k0+ty+j)*N + n];
    __syncthreads();
    int k = k0 + tx;
    int nb = blockIdx.x*32;
    #pragma unroll
    for (int j = 0; j < 32; j += 8)
        Wt[((size_t)(nb+ty+j)*rs + ro)*K + k] = __float2bfloat16(t[tx][ty+j]);
}

// ---------------- adafm projection -------------------------------------------
__global__ void proj_kernel(const float* __restrict__ ada, const float* __restrict__ pw,
                            const float* __restrict__ pb)
{
    int j = blockIdx.x * blockDim.x + threadIdx.x;
    int b = blockIdx.y;
    float acc = pb[j];
    const float* ap = ada + b*DIM_;
    for (int d = 0; d < DIM_; ++d) {
        float a = ap[d];
        float s = a / (1.0f + __expf(-a));
        acc = fmaf(s, pw[d*512 + j], acc);
    }
    g_t[b*512 + j] = acc;
}

__global__ void kconv_kernel()
{
    int d = threadIdx.x;
    int which = blockIdx.x, b = blockIdx.y;
    const float* F = g_t + b*512 + which*256;
    float acc = 0.f;
    for (int m = 0; m < 256; ++m) {
        int md = (m * d) & 255;
        acc = fmaf(F[m], cospif((float)md * (1.0f/128.0f)), acc);
    }
    g_kc[(which*2 + b)*256 + d] = acc * (1.0f/256.0f);
}

__global__ void kmat_kernel()
{
    int wb = blockIdx.x;
    int n = threadIdx.x;
    const float* kk = g_kc + wb*256;
    __nv_bfloat16* Km = g_kmat + (size_t)wb*256*256 + n*256;
    #pragma unroll 4
    for (int k = 0; k < 256; ++k)
        Km[k] = __float2bfloat16(kk[(n - k) & 255]);
}

__global__ __launch_bounds__(256) void gather_kernel(const float* __restrict__ X,
                                                     __nv_bfloat16* __restrict__ Xp)
{
    int b = blockIdx.y;
    int p = blockIdx.x*4 + (threadIdx.x >> 6);
    int q = threadIdx.x & 63;
    int r = q >> 2, cs = (q & 3)*4;
    int ib = p >> 6, jb = p & 63;
    float4 v = *(const float4*)(X + ((size_t)(b*SEQL + ib*16 + r))*DIM_ + jb*16 + cs);
    uint2 o;
    o.x = packbf(v.x, v.y);
    o.y = packbf(v.z, v.w);
    *(uint2*)(Xp + ((size_t)(b*NPATB + p))*256 + r*16 + cs) = o;
}

// ------------- rotary + justnorm -> bf16 q(×8·log2e)/k/v ---------------------
__global__ __launch_bounds__(512) void rotnorm_kernel(const float* __restrict__ fc,
                                                      const float* __restrict__ fs,
                                                      const float* __restrict__ sqk)
{
    int row = blockIdx.x;
    int s = row & (SEQL - 1);
    int b = row >> 11;
    int h = threadIdx.x >> 5;
    int i = threadIdx.x & 31;
    float c = fc[s*32 + i], sn = fs[s*32 + i];
    size_t gin = (size_t)row*NQKV + h*64 + 2*i;
    __nv_bfloat162 qv = *(const __nv_bfloat162*)(g_qkvb + gin);
    __nv_bfloat162 kv = *(const __nv_bfloat162*)(g_qkvb + gin + DIM_);
    __nv_bfloat162 vv = *(const __nv_bfloat162*)(g_qkvb + gin + 2*DIM_);
    float qa = __bfloat162float(qv.x), qb = __bfloat162float(qv.y);
    float ka = __bfloat162float(kv.x), kb = __bfloat162float(kv.y);
    float ra = qa*c - qb*sn, rb = qa*sn + qb*c;
    float ta = ka*c - kb*sn, tb = ka*sn + kb*c;
    float sq = ra*ra + rb*rb, sk = ta*ta + tb*tb;
    #pragma unroll
    for (int o = 16; o; o >>= 1) {
        sq += __shfl_xor_sync(0xffffffffu, sq, o);
        sk += __shfl_xor_sync(0xffffffffu, sk, o);
    }
    float invq = 1.0f / fmaxf(sqrtf(sq), 1e-12f);
    float invk = 1.0f / fmaxf(sqrtf(sk), 1e-12f);
    float sa = sqk[h*64 + 2*i]   * 32.0f;
    float sb = sqk[h*64 + 2*i+1] * 32.0f;
    size_t go = ((size_t)(b*NH_ + h)*SEQL + s)*64 + 2*i;
    // fold score scale sqrt(HD)=8 AND log2(e) into q => softmax works in exp2 domain
    const float QS = 8.0f * 1.4426950408889634f;
    *(__nv_bfloat162*)(g_qb + go) = __floats2bfloat162_rn(ra*invq*sa*QS, rb*invq*sb*QS);
    *(__nv_bfloat162*)(g_kb + go) = __floats2bfloat162_rn(ta*invk*sa, tb*invk*sb);
    *(__nv_bfloat162*)(g_vb + go) = vv;
}

// ------------- flash attention, bf16 mma.sync, paired-x4, exp2 softmax -------
#define APAD 72
__global__ __launch_bounds__(256) void attn_kernel()
{
    __shared__ __nv_bfloat16 sQ[128][APAD];
    __shared__ __nv_bfloat16 sK[64][APAD];
    __shared__ __nv_bfloat16 sV[64][APAD];
    int tid = threadIdx.x, lane = tid & 31, wid = tid >> 5;
    int q0 = blockIdx.x * 128;
    int h = blockIdx.y, b = blockIdx.z;
    size_t base = ((size_t)(b*NH_ + h))*SEQL*HD_;
    const __nv_bfloat16* Qg = g_qb + base;
    const __nv_bfloat16* Kg = g_kb + base;
    const __nv_bfloat16* Vg = g_vb + base;

    {
        int r = tid >> 1, c = (tid & 1)*32;
        const uint4* src = (const uint4*)(Qg + (size_t)(q0 + r)*64 + c);
        uint4 v0 = src[0], v1 = src[1], v2 = src[2], v3 = src[3];
        uint4* d = (uint4*)&sQ[r][c];
        d[0] = v0; d[1] = v1; d[2] = v2; d[3] = v3;
    }

    int kvr = tid >> 2, kvc = (tid & 3)*16;
    uint4 pk0, pk1, pv0, pv1;
    {
        pk0 = *(const uint4*)(Kg + (size_t)kvr*64 + kvc);
        pk1 = *(const uint4*)(Kg + (size_t)kvr*64 + kvc + 8);
        pv0 = *(const uint4*)(Vg + (size_t)kvr*64 + kvc);
        pv1 = *(const uint4*)(Vg + (size_t)kvr*64 + kvc + 8);
    }
    __syncthreads();

    uint32_t aq[4][4];
    {
        int r = wid*16 + (lane & 15);
        int cb = (lane >> 4)*8;
        #pragma unroll
        for (int kc = 0; kc < 4; kc++)
            ldsm_x4(aq[kc], smem_u32(&sQ[r][kc*16 + cb]));
    }

    int b_r2 = ((lane >> 4) << 3) + (lane & 7);
    int b_k2 = ((lane >> 3) & 1)*8;
    int v_r  = lane & 15;
    int v_c2 = ((lane >> 4) << 3);

    float mrun[2] = {-1e30f, -1e30f}, lrun[2] = {0.f, 0.f};
    float oacc[8][4];
    #pragma unroll
    for (int nf = 0; nf < 8; nf++)
        #pragma unroll
        for (int q = 0; q < 4; q++) oacc[nf][q] = 0.f;

    for (int t = 0; t < SEQL/64; t++) {
        *(uint4*)&sK[kvr][kvc]     = pk0;
        *(uint4*)&sK[kvr][kvc + 8] = pk1;
        *(uint4*)&sV[kvr][kvc]     = pv0;
        *(uint4*)&sV[kvr][kvc + 8] = pv1;
        __syncthreads();
        if (t + 1 < SEQL/64) {
            const __nv_bfloat16* Kt = Kg + (size_t)(t+1)*64*64;
            const __nv_bfloat16* Vt = Vg + (size_t)(t+1)*64*64;
            pk0 = *(const uint4*)(Kt + (size_t)kvr*64 + kvc);
            pk1 = *(const uint4*)(Kt + (size_t)kvr*64 + kvc + 8);
            pv0 = *(const uint4*)(Vt + (size_t)kvr*64 + kvc);
            pv1 = *(const uint4*)(Vt + (size_t)kvr*64 + kvc + 8);
        }

        float s[8][4];
        #pragma unroll
        for (int nf = 0; nf < 8; nf++)
            #pragma unroll
            for (int q = 0; q < 4; q++) s[nf][q] = 0.f;
        #pragma unroll
        for (int kc = 0; kc < 4; kc++) {
            uint32_t bk[8][2];
            #pragma unroll
            for (int ntp = 0; ntp < 4; ntp++) {
                uint32_t b4[4];
                ldsm_x4(b4, smem_u32(&sK[ntp*16 + b_r2][kc*16 + b_k2]));
                bk[2*ntp][0]   = b4[0]; bk[2*ntp][1]   = b4[1];
                bk[2*ntp+1][0] = b4[2]; bk[2*ntp+1][1] = b4[3];
            }
            #pragma unroll
            for (int nf = 0; nf < 8; nf++)
                mma16816(s[nf], aq[kc], bk[nf]);
        }

        #pragma unroll
        for (int hh = 0; hh < 2; hh++) {
            float tm = -1e30f;
            #pragma unroll
            for (int nf = 0; nf < 8; nf++)
                tm = fmaxf(tm, fmaxf(s[nf][hh*2], s[nf][hh*2+1]));
            tm = fmaxf(tm, __shfl_xor_sync(0xffffffffu, tm, 1));
            tm = fmaxf(tm, __shfl_xor_sync(0xffffffffu, tm, 2));
            float mn = fmaxf(mrun[hh], tm);
            float f = exp2f(mrun[hh] - mn);
            float rs = 0.f;
            #pragma unroll
            for (int nf = 0; nf < 8; nf++) {
                float p0 = exp2f(s[nf][hh*2]   - mn);
                float p1 = exp2f(s[nf][hh*2+1] - mn);
                s[nf][hh*2] = p0; s[nf][hh*2+1] = p1;
                rs += p0 + p1;
            }
            rs += __shfl_xor_sync(0xffffffffu, rs, 1);
            rs += __shfl_xor_sync(0xffffffffu, rs, 2);
            lrun[hh] = lrun[hh]*f + rs;
            mrun[hh] = mn;
            #pragma unroll
            for (int nf = 0; nf < 8; nf++) {
                oacc[nf][hh*2]   *= f;
                oacc[nf][hh*2+1] *= f;
            }
        }

        uint32_t pf[4][4];
        #pragma unroll
        for (int kc = 0; kc < 4; kc++) {
            pf[kc][0] = packbf(s[2*kc][0],   s[2*kc][1]);
            pf[kc][1] = packbf(s[2*kc][2],   s[2*kc][3]);
            pf[kc][2] = packbf(s[2*kc+1][0], s[2*kc+1][1]);
            pf[kc][3] = packbf(s[2*kc+1][2], s[2*kc+1][3]);
        }

        #pragma unroll
        for (int kc = 0; kc < 4; kc++) {
            uint32_t bv[8][2];
            #pragma unroll
            for (int nfp = 0; nfp < 4; nfp++) {
                uint32_t b4[4];
                ldsm_x4t(b4, smem_u32(&sV[kc*16 + v_r][nfp*16 + v_c2]));
                bv[2*nfp][0]   = b4[0]; bv[2*nfp][1]   = b4[1];
                bv[2*nfp+1][0] = b4[2]; bv[2*nfp+1][1] = b4[3];
            }
            #pragma unroll
            for (int nf = 0; nf < 8; nf++)
                mma16816(oacc[nf], pf[kc], bv[nf]);
        }
        __syncthreads();
    }

    int r0 = wid*16 + (lane >> 2);
    #pragma unroll
    for (int hh = 0; hh < 2; hh++) {
        float inv = 1.0f / lrun[hh];
        int row = q0 + r0 + hh*8;
        size_t o = ((size_t)(b*SEQL) + row)*DIM_ + h*64 + (lane & 3)*2;
        #pragma unroll
        for (int nf = 0; nf < 8; nf++) {
            __nv_bfloat162 p = __floats2bfloat162_rn(oacc[nf][hh*2]*inv, oacc[nf][hh*2+1]*inv);
            *(__nv_bfloat162*)(g_attnb + o + nf*8) = p;
        }
    }
}

// ------------- combine (H in bf16; optional fused patch-gather output) -------
__device__ __forceinline__ float block_sum(float v, float* shm)
{
    #pragma unroll
    for (int o = 16; o; o >>= 1) v += __shfl_xor_sync(0xffffffffu, v, o);
    __syncthreads();
    if ((threadIdx.x & 31) == 0) shm[threadIdx.x >> 5] = v;
    __syncthreads();
    if (threadIdx.x < 32) {
        float t = (threadIdx.x < 8) ? shm[threadIdx.x] : 0.f;
        #pragma unroll
        for (int o = 4; o; o >>= 1) t += __shfl_xor_sync(0xffffffffu, t, o);
        if (threadIdx.x == 0) shm[0] = t;
    }
    __syncthreads();
    return shm[0];
}

__global__ __launch_bounds__(256) void combine_kernel(const float* __restrict__ X,
                                                      const __nv_bfloat16* __restrict__ H,
                                                      const float* __restrict__ alpha,
                                                      float* __restrict__ Out,
                                                      __nv_bfloat16* __restrict__ Xp)
{
    __shared__ float shm[8];
    int row = blockIdx.x;
    const float* xp = X + (size_t)row*DIM_;
    const __nv_bfloat16* hp = H + (size_t)row*DIM_;
    float xv[4], hv[4];
    float sx = 0.f, sh = 0.f;
    #pragma unroll
    for (int i = 0; i < 4; i++) {
        int j = threadIdx.x + i*256;
        xv[i] = xp[j]; hv[i] = __bfloat162float(hp[j]);
        sx = fmaf(xv[i], xv[i], sx);
        sh = fmaf(hv[i], hv[i], sh);
    }
    float nx = block_sum(sx, shm);
    float nh = block_sum(sh, shm);
    float invx = 1.0f / fmaxf(sqrtf(nx), 1e-12f);
    float invh = 1.0f / fmaxf(sqrtf(nh), 1e-12f);
    float yv[4]; float sy = 0.f;
    #pragma unroll
    for (int i = 0; i < 4; i++) {
        int j = threadIdx.x + i*256;
        float lr = fabsf(alpha[j] * 1.6f);
        float hn = xv[i]*invx;
        float y = hn + lr*(hv[i]*invh - hn);
        yv[i] = y; sy = fmaf(y, y, sy);
    }
    float ny = block_sum(sy, shm);
    float invy = 1.0f / fmaxf(sqrtf(ny), 1e-12f);
    int bb = row >> 11, ss = row & (SEQL-1);
    int ib = ss >> 4, rr = ss & 15;
    #pragma unroll
    for (int i = 0; i < 4; i++) {
        int j = threadIdx.x + i*256;
        float y = yv[i]*invy;
        Out[(size_t)row*DIM_ + j] = y;
        if (Xp) {
            int p = ib*64 + (j >> 4);
            Xp[((size_t)(bb*NPATB + p))*256 + rr*16 + (j & 15)] = __float2bfloat16(y);
        }
    }
}

// ------------------------------- launcher -------------------------------------
extern "C" void kernel_launch(void* const* d_in, const int* in_sizes, int n_in,
                              void* d_out, int out_size)
{
    const float* x   = (const float*)d_in[0];
    const float* fc  = (const float*)d_in[1];
    const float* fs  = (const float*)d_in[2];
    const float* ada = (const float*)d_in[3];
    const float* wq  = (const float*)d_in[4];
    const float* wk  = (const float*)d_in[5];
    const float* wv  = (const float*)d_in[6];
    const float* wo  = (const float*)d_in[7];
    const float* sqk = (const float*)d_in[8];
    const float* w1  = (const float*)d_in[9];
    const float* w2  = (const float*)d_in[10];
    const float* w3  = (const float*)d_in[11];
    const float* su  = (const float*)d_in[12];
    const float* sv  = (const float*)d_in[13];
    const float* pw  = (const float*)d_in[14];
    const float* pb  = (const float*)d_in[15];
    const float* aat = (const float*)d_in[16];
    const float* aml = (const float*)d_in[17];
    float* out = (float*)d_out;

    float *x1;
    __nv_bfloat16 *xmodb, *attnb, *x1mb, *hhb, *qkvb, *kmat, *xpat, *hab, *hmb;
    __nv_bfloat16 *wqkvt, *wot, *w13t, *w2t;
    cudaGetSymbolAddress((void**)&x1,   g_x1);
    cudaGetSymbolAddress((void**)&xmodb, g_xmodb);
    cudaGetSymbolAddress((void**)&attnb, g_attnb);
    cudaGetSymbolAddress((void**)&x1mb,  g_x1mb);
    cudaGetSymbolAddress((void**)&hhb,   g_hhb);
    cudaGetSymbolAddress((void**)&qkvb,  g_qkvb);
    cudaGetSymbolAddress((void**)&kmat,  g_kmat);
    cudaGetSymbolAddress((void**)&xpat,  g_xpat);
    cudaGetSymbolAddress((void**)&hab,   g_hab);
    cudaGetSymbolAddress((void**)&hmb,   g_hmb);
    cudaGetSymbolAddress((void**)&wqkvt, g_wqkvt);
    cudaGetSymbolAddress((void**)&wot,   g_wot);
    cudaGetSymbolAddress((void**)&w13t,  g_w13t);
    cudaGetSymbolAddress((void**)&w2t,   g_w2t);

    cudaFuncSetAttribute(tgemm_epi<EpiBF16>,   cudaFuncAttributeMaxDynamicSharedMemorySize, GEMM_SMEM);
    cudaFuncSetAttribute(tgemm_epi<EpiSwiglu>, cudaFuncAttributeMaxDynamicSharedMemorySize, GEMM_SMEM);
    cudaFuncSetAttribute(tgemm_mod,            cudaFuncAttributeMaxDynamicSharedMemorySize, GEMM_SMEM);

    // 0. weight transposes (bf16, [N][K]); qkv packed; w1/w3 interleaved
    wtrans_kernel<<<dim3(DIM_/32, DIM_/32), dim3(32,8)>>>(wq, wqkvt,               DIM_, DIM_, 1, 0);
    wtrans_kernel<<<dim3(DIM_/32, DIM_/32), dim3(32,8)>>>(wk, wqkvt + DIM_*DIM_,   DIM_, DIM_, 1, 0);
    wtrans_kernel<<<dim3(DIM_/32, DIM_/32), dim3(32,8)>>>(wv, wqkvt + 2*DIM_*DIM_, DIM_, DIM_, 1, 0);
    wtrans_kernel<<<dim3(DIM_/32, DIM_/32), dim3(32,8)>>>(wo, wot, DIM_, DIM_, 1, 0);
    wtrans_kernel<<<dim3(HID_/32, DIM_/32), dim3(32,8)>>>(w1, w13t, DIM_, HID_, 2, 0);
    wtrans_kernel<<<dim3(HID_/32, DIM_/32), dim3(32,8)>>>(w3, w13t, DIM_, HID_, 2, 1);
    wtrans_kernel<<<dim3(DIM_/32, HID_/32), dim3(32,8)>>>(w2, w2t, HID_, DIM_, 1, 0);

    // 1. adafm projection + conv kernel matrices
    proj_kernel<<<dim3(2, 2), 256>>>(ada, pw, pb);
    kconv_kernel<<<dim3(2, 2), 256>>>();
    kmat_kernel<<<4, 256>>>();

    // 2. attention branch
    gather_kernel<<<dim3(NPATB/4, B_), 256>>>(x, xpat);
    tgemm_mod<<<dim3(2, NPATB/256, B_), 256, GEMM_SMEM>>>(xpat, kmat, xmodb);
    tgemm_epi<EpiBF16><<<dim3(NQKV/128, NTOK/256), 256, GEMM_SMEM>>>(xmodb, wqkvt, DIM_, EpiBF16{qkvb, NQKV});
    rotnorm_kernel<<<NTOK, 512>>>(fc, fs, sqk);
    attn_kernel<<<dim3(SEQL/128, NH_, B_), 256>>>();
    tgemm_epi<EpiBF16><<<dim3(DIM_/128, NTOK/256), 256, GEMM_SMEM>>>(attnb, wot, DIM_, EpiBF16{hab, DIM_});
    combine_kernel<<<NTOK, 256>>>(x, hab, aat, x1, xpat);   // fused gather for MLP branch

    // 3. mlp branch
    tgemm_mod<<<dim3(2, NPATB/256, B_), 256, GEMM_SMEM>>>(xpat, kmat + 2*256*256, x1mb);
    tgemm_epi<EpiSwiglu><<<dim3(N13/128, NTOK/256), 256, GEMM_SMEM>>>(x1mb, w13t, DIM_, EpiSwiglu{hhb, su, sv});
    tgemm_epi<EpiBF16><<<dim3(DIM_/128, NTOK/256), 256, GEMM_SMEM>>>(hhb, w2t, HID_, EpiBF16{hmb, DIM_});
    combine_kernel<<<NTOK, 256>>>(x1, hmb, aml, out, nullptr);
}

// round 14
// speedup vs baseline: 1.0440x; 1.0440x over previous
#include <cuda_runtime.h>
#include <cuda_bf16.h>
#include <math.h>
#include <cstdint>

#define B_    2
#define SEQL  2048
#define DIM_  1024
#define NH_   16
#define HD_   64
#define HID_  2816
#define NTOK  (B_*SEQL)          // 4096
#define NQKV  (3*DIM_)           // 3072
#define N13   (2*HID_)           // 5632
#define NPATB 8192               // patches per batch (128*64)

// ---------------- scratch (device globals; no allocations allowed) ----------
__device__ float g_t[B_*512];
__device__ float g_kc[4*256];
__device__ float g_x1[NTOK*DIM_];
// bf16 activations
__device__ __nv_bfloat16 g_qkvb[NTOK*NQKV];
__device__ __nv_bfloat16 g_qb[NTOK*DIM_];
__device__ __nv_bfloat16 g_kb[NTOK*DIM_];
__device__ __nv_bfloat16 g_vb[NTOK*DIM_];
__device__ __nv_bfloat16 g_xmodb[NTOK*DIM_];
__device__ __nv_bfloat16 g_attnb[NTOK*DIM_];
__device__ __nv_bfloat16 g_x1mb[NTOK*DIM_];
__device__ __nv_bfloat16 g_hhb[NTOK*HID_];
__device__ __nv_bfloat16 g_hab[NTOK*DIM_];
__device__ __nv_bfloat16 g_hmb[NTOK*DIM_];
// modulate-as-GEMM scratch
__device__ __nv_bfloat16 g_kmat[4*256*256];        // [which][b][n][k]
__device__ __nv_bfloat16 g_xpat[NTOK*DIM_];        // patch-major input
// bf16 transposed weights [N][K]
__device__ __nv_bfloat16 g_wqkvt[NQKV*DIM_];
__device__ __nv_bfloat16 g_wot[DIM_*DIM_];
__device__ __nv_bfloat16 g_w13t[N13*DIM_];         // interleaved: row 2j=w1_j, 2j+1=w3_j
__device__ __nv_bfloat16 g_w2t[DIM_*HID_];

// ====================== mma.sync helpers (family-safe) =======================
__device__ __forceinline__ uint32_t smem_u32(const void* p) {
    uint32_t a;
    asm("{ .reg .u64 t; cvta.to.shared.u64 t, %1; cvt.u32.u64 %0, t; }" : "=r"(a) : "l"(p));
    return a;
}
__device__ __forceinline__ void ldsm_x4(uint32_t* r, uint32_t addr) {
    asm volatile("ldmatrix.sync.aligned.m8n8.x4.shared.b16 {%0,%1,%2,%3}, [%4];"
                 : "=r"(r[0]), "=r"(r[1]), "=r"(r[2]), "=r"(r[3]) : "r"(addr));
}
__device__ __forceinline__ void ldsm_x4t(uint32_t* r, uint32_t addr) {
    asm volatile("ldmatrix.sync.aligned.m8n8.x4.trans.shared.b16 {%0,%1,%2,%3}, [%4];"
                 : "=r"(r[0]), "=r"(r[1]), "=r"(r[2]), "=r"(r[3]) : "r"(addr));
}
__device__ __forceinline__ void mma16816(float* c, const uint32_t* a, const uint32_t* b) {
    asm volatile("mma.sync.aligned.m16n8k16.row.col.f32.bf16.bf16.f32 "
                 "{%0,%1,%2,%3}, {%4,%5,%6,%7}, {%8,%9}, {%0,%1,%2,%3};"
                 : "+f"(c[0]), "+f"(c[1]), "+f"(c[2]), "+f"(c[3])
                 : "r"(a[0]), "r"(a[1]), "r"(a[2]), "r"(a[3]), "r"(b[0]), "r"(b[1]));
}
__device__ __forceinline__ uint32_t packbf(float lo, float hi) {
    __nv_bfloat162 p = __floats2bfloat162_rn(lo, hi);
    return *(uint32_t*)&p;
}
#define CPASYNC16(saddr, gptr) \
    asm volatile("cp.async.cg.shared.global [%0], [%1], 16;" :: "r"(saddr), "l"(gptr))
#define CP_COMMIT() asm volatile("cp.async.commit_group;" ::: "memory")
#define CP_WAIT(n)  asm volatile("cp.async.wait_group %0;" :: "n"(n) : "memory")

// ============== cp.async 3-stage mma.sync GEMM, 256x128 CTA tile =============
#define SPAD   40
#define STG    3
#define ASTAGE (256*SPAD*2)
#define BSTAGE (128*SPAD*2)
#define STAGEB (ASTAGE+BSTAGE)
#define GEMM_SMEM (STG*STAGEB)

struct EpiBF16 {
    __nv_bfloat16* C; int N;
    __device__ __forceinline__ void store(int r0, int col, const float* a) const {
        *(uint32_t*)(C + (size_t)r0*N + col)     = packbf(a[0], a[1]);
        *(uint32_t*)(C + (size_t)(r0+8)*N + col) = packbf(a[2], a[3]);
    }
};
struct EpiSwiglu {
    __nv_bfloat16* out; const float* su; const float* sv;
    __device__ __forceinline__ void store(int r0, int col, const float* a) const {
        int j = col >> 1;
        float svj = sv[j] * 53.06599665f;
        float suj = su[j];
        float z0 = a[0]*svj, z1 = a[2]*svj;
        float h0 = z0 / (1.f + __expf(-z0)) * (a[1]*suj);
        float h1 = z1 / (1.f + __expf(-z1)) * (a[3]*suj);
        out[(size_t)r0*HID_ + j]     = __float2bfloat16(h0);
        out[(size_t)(r0+8)*HID_ + j] = __float2bfloat16(h1);
    }
};
struct EpiMod {
    __nv_bfloat16* Y;
    __device__ __forceinline__ void store(int p, int n, const float* a) const {
        int grow0 = ((p >> 6) << 4) + (n >> 4);
        int gcol  = ((p & 63) << 4) + (n & 15);
        int grow1 = (((p+8) >> 6) << 4) + (n >> 4);
        int gcol1 = (((p+8) & 63) << 4) + (n & 15);
        *(uint32_t*)(Y + (size_t)grow0*DIM_ + gcol)  = packbf(a[0], a[1]);
        *(uint32_t*)(Y + (size_t)grow1*DIM_ + gcol1) = packbf(a[2], a[3]);
    }
};

template<class Epi>
__device__ __forceinline__ void tgemm_core(const __nv_bfloat16* __restrict__ A,
                                           const __nv_bfloat16* __restrict__ Bt,
                                           int K, uint32_t sbase, const Epi& epi)
{
    int tid = threadIdx.x, lane = tid & 31, wid = tid >> 5;
    int wr = wid >> 1, wc = wid & 1;
    int row0 = blockIdx.y * 256, col0 = blockIdx.x * 128;

    int arow = tid >> 2, aseg = tid & 3;
    const __nv_bfloat16* Ag = A  + (size_t)(row0 + arow)*K + aseg*8;
    const __nv_bfloat16* Bg = Bt + (size_t)(col0 + arow)*K + aseg*8;
    uint32_t sAo = arow*(SPAD*2) + aseg*16;
    uint32_t sBo = ASTAGE + arow*(SPAD*2) + aseg*16;

    int NC = K >> 5;

    #pragma unroll
    for (int s = 0; s < STG-1; s++) {
        uint32_t st = sbase + s*STAGEB;
        const __nv_bfloat16* Ap = Ag + (size_t)s*32;
        const __nv_bfloat16* Bp = Bg + (size_t)s*32;
        #pragma unroll
        for (int i = 0; i < 4; i++)
            CPASYNC16(st + sAo + i*64*(SPAD*2), Ap + (size_t)i*64*K);
        #pragma unroll
        for (int i = 0; i < 2; i++)
            CPASYNC16(st + sBo + i*64*(SPAD*2), Bp + (size_t)i*64*K);
        CP_COMMIT();
    }

    float acc[4][8][4];
    #pragma unroll
    for (int i = 0; i < 4; i++)
        #pragma unroll
        for (int j = 0; j < 8; j++)
            #pragma unroll
            for (int q = 0; q < 4; q++) acc[i][j][q] = 0.f;

    int aq = lane >> 3, arw = lane & 7;
    int a_r = (aq & 1)*8 + arw;
    int a_kb = (aq >> 1)*16;
    int b_r2 = ((lane >> 4) << 3) + (lane & 7);
    int b_kb2 = ((lane >> 3) & 1)*16;

    int buf = 0;
    for (int c = 0; c < NC; c++) {
        CP_WAIT(STG-2);
        __syncthreads();

        if (c + STG-1 < NC) {
            int pb = buf - 1; if (pb < 0) pb += STG;
            uint32_t st = sbase + pb*STAGEB;
            const __nv_bfloat16* Ap = Ag + (size_t)(c+STG-1)*32;
            const __nv_bfloat16* Bp = Bg + (size_t)(c+STG-1)*32;
            #pragma unroll
            for (int i = 0; i < 4; i++)
                CPASYNC16(st + sAo + i*64*(SPAD*2), Ap + (size_t)i*64*K);
            #pragma unroll
            for (int i = 0; i < 2; i++)
                CPASYNC16(st + sBo + i*64*(SPAD*2), Bp + (size_t)i*64*K);
        }
        CP_COMMIT();

        uint32_t aBase = sbase + buf*STAGEB;
        uint32_t bBase = aBase + ASTAGE;
        #pragma unroll
        for (int ks = 0; ks < 2; ks++) {
            uint32_t afr[4][4], bfr[8][2];
            #pragma unroll
            for (int mt = 0; mt < 4; mt++)
                ldsm_x4(afr[mt], aBase + (wr*64 + mt*16 + a_r)*(SPAD*2) + ks*32 + a_kb);
            #pragma unroll
            for (int ntp = 0; ntp < 4; ntp++) {
                uint32_t b4[4];
                ldsm_x4(b4, bBase + (wc*64 + ntp*16 + b_r2)*(SPAD*2) + ks*32 + b_kb2);
                bfr[2*ntp][0]   = b4[0]; bfr[2*ntp][1]   = b4[1];
                bfr[2*ntp+1][0] = b4[2]; bfr[2*ntp+1][1] = b4[3];
            }
            #pragma unroll
            for (int mt = 0; mt < 4; mt++)
                #pragma unroll
                for (int nt = 0; nt < 8; nt++)
                    mma16816(acc[mt][nt], afr[mt], bfr[nt]);
        }
        __syncthreads();
        buf++; if (buf == STG) buf = 0;
    }

    int cr = lane >> 2, cc = (lane & 3)*2;
    #pragma unroll
    for (int mt = 0; mt < 4; mt++) {
        int r0 = row0 + wr*64 + mt*16 + cr;
        #pragma unroll
        for (int nt = 0; nt < 8; nt++)
            epi.store(r0, col0 + wc*64 + nt*8 + cc, acc[mt][nt]);
    }
}

template<class Epi>
__global__ __launch_bounds__(256) void tgemm_epi(const __nv_bfloat16* __restrict__ A,
                                                 const __nv_bfloat16* __restrict__ Bt,
                                                 int K, Epi epi)
{
    extern __shared__ char smemraw[];
    tgemm_core<Epi>(A, Bt, K, smem_u32(smemraw), epi);
}

__global__ __launch_bounds__(256) void tgemm_mod(const __nv_bfloat16* __restrict__ A,
                                                 const __nv_bfloat16* __restrict__ Bt,
                                                 __nv_bfloat16* __restrict__ Y)
{
    extern __shared__ char smemraw[];
    int z = blockIdx.z;
    EpiMod epi{ Y + (size_t)z*SEQL*DIM_ };
    tgemm_core<EpiMod>(A + (size_t)z*NPATB*256, Bt + (size_t)z*256*256,
                       256, smem_u32(smemraw), epi);
}

// -------- weight transpose + bf16 convert ------------------------------------
__global__ void wtrans_kernel(const float* __restrict__ W, __nv_bfloat16* __restrict__ Wt,
                              int K, int N, int rs, int ro)
{
    __shared__ float t[32][33];
    int tx = threadIdx.x, ty = threadIdx.y;
    int n = blockIdx.x*32 + tx;
    int k0 = blockIdx.y*32;
    #pragma unroll
    for (int j = 0; j < 32; j += 8)
        t[ty+j][tx] = W[(size_t)(k0+ty+j)*N + n];
    __syncthreads();
    int k = k0 + tx;
    int nb = blockIdx.x*32;
    #pragma unroll
    for (int j = 0; j < 32; j += 8)
        Wt[((size_t)(nb+ty+j)*rs + ro)*K + k] = __float2bfloat16(t[tx][ty+j]);
}

// ---------------- adafm projection -------------------------------------------
__global__ void proj_kernel(const float* __restrict__ ada, const float* __restrict__ pw,
                            const float* __restrict__ pb)
{
    int j = blockIdx.x * blockDim.x + threadIdx.x;
    int b = blockIdx.y;
    float acc = pb[j];
    const float* ap = ada + b*DIM_;
    for (int d = 0; d < DIM_; ++d) {
        float a = ap[d];
        float s = a / (1.0f + __expf(-a));
        acc = fmaf(s, pw[d*512 + j], acc);
    }
    g_t[b*512 + j] = acc;
}

__global__ void kconv_kernel()
{
    int d = threadIdx.x;
    int which = blockIdx.x, b = blockIdx.y;
    const float* F = g_t + b*512 + which*256;
    float acc = 0.f;
    for (int m = 0; m < 256; ++m) {
        int md = (m * d) & 255;
        acc = fmaf(F[m], cospif((float)md * (1.0f/128.0f)), acc);
    }
    g_kc[(which*2 + b)*256 + d] = acc * (1.0f/256.0f);
}

__global__ void kmat_kernel()
{
    int wb = blockIdx.x;
    int n = threadIdx.x;
    const float* kk = g_kc + wb*256;
    __nv_bfloat16* Km = g_kmat + (size_t)wb*256*256 + n*256;
    #pragma unroll 4
    for (int k = 0; k < 256; ++k)
        Km[k] = __float2bfloat16(kk[(n - k) & 255]);
}

__global__ __launch_bounds__(256) void gather_kernel(const float* __restrict__ X,
                                                     __nv_bfloat16* __restrict__ Xp)
{
    int b = blockIdx.y;
    int p = blockIdx.x*4 + (threadIdx.x >> 6);
    int q = threadIdx.x & 63;
    int r = q >> 2, cs = (q & 3)*4;
    int ib = p >> 6, jb = p & 63;
    float4 v = *(const float4*)(X + ((size_t)(b*SEQL + ib*16 + r))*DIM_ + jb*16 + cs);
    uint2 o;
    o.x = packbf(v.x, v.y);
    o.y = packbf(v.z, v.w);
    *(uint2*)(Xp + ((size_t)(b*NPATB + p))*256 + r*16 + cs) = o;
}

// ------------- rotary + justnorm -> bf16 q(×8·log2e)/k/v ---------------------
__global__ __launch_bounds__(512) void rotnorm_kernel(const float* __restrict__ fc,
                                                      const float* __restrict__ fs,
                                                      const float* __restrict__ sqk)
{
    int row = blockIdx.x;
    int s = row & (SEQL - 1);
    int b = row >> 11;
    int h = threadIdx.x >> 5;
    int i = threadIdx.x & 31;
    float c = fc[s*32 + i], sn = fs[s*32 + i];
    size_t gin = (size_t)row*NQKV + h*64 + 2*i;
    __nv_bfloat162 qv = *(const __nv_bfloat162*)(g_qkvb + gin);
    __nv_bfloat162 kv = *(const __nv_bfloat162*)(g_qkvb + gin + DIM_);
    __nv_bfloat162 vv = *(const __nv_bfloat162*)(g_qkvb + gin + 2*DIM_);
    float qa = __bfloat162float(qv.x), qb = __bfloat162float(qv.y);
    float ka = __bfloat162float(kv.x), kb = __bfloat162float(kv.y);
    float ra = qa*c - qb*sn, rb = qa*sn + qb*c;
    float ta = ka*c - kb*sn, tb = ka*sn + kb*c;
    float sq = ra*ra + rb*rb, sk = ta*ta + tb*tb;
    #pragma unroll
    for (int o = 16; o; o >>= 1) {
        sq += __shfl_xor_sync(0xffffffffu, sq, o);
        sk += __shfl_xor_sync(0xffffffffu, sk, o);
    }
    float invq = 1.0f / fmaxf(sqrtf(sq), 1e-12f);
    float invk = 1.0f / fmaxf(sqrtf(sk), 1e-12f);
    float sa = sqk[h*64 + 2*i]   * 32.0f;
    float sb = sqk[h*64 + 2*i+1] * 32.0f;
    size_t go = ((size_t)(b*NH_ + h)*SEQL + s)*64 + 2*i;
    // fold score scale sqrt(HD)=8 AND log2(e) into q => softmax works in exp2 domain
    const float QS = 8.0f * 1.4426950408889634f;
    *(__nv_bfloat162*)(g_qb + go) = __floats2bfloat162_rn(ra*invq*sa*QS, rb*invq*sb*QS);
    *(__nv_bfloat162*)(g_kb + go) = __floats2bfloat162_rn(ta*invk*sa, tb*invk*sb);
    *(__nv_bfloat162*)(g_vb + go) = vv;
}

// ------------- flash attention: fixed-shift softmax (no online max) ----------
// |q·k| <= |q||k| = 1 (unit rows, sqk_eff==1) => exp2-score in [-11.6, 11.6].
// exp2(s-12) in [2^-24, 1]: no overflow/underflow; per-lane partial sums,
// single quad-reduce at the end. No running max, no rescales.
#define APAD 72
#define SHIFT_ 12.0f
__global__ __launch_bounds__(256) void attn_kernel()
{
    __shared__ __nv_bfloat16 sQ[128][APAD];
    __shared__ __nv_bfloat16 sK[64][APAD];
    __shared__ __nv_bfloat16 sV[64][APAD];
    int tid = threadIdx.x, lane = tid & 31, wid = tid >> 5;
    int q0 = blockIdx.x * 128;
    int h = blockIdx.y, b = blockIdx.z;
    size_t base = ((size_t)(b*NH_ + h))*SEQL*HD_;
    const __nv_bfloat16* Qg = g_qb + base;
    const __nv_bfloat16* Kg = g_kb + base;
    const __nv_bfloat16* Vg = g_vb + base;

    {
        int r = tid >> 1, c = (tid & 1)*32;
        const uint4* src = (const uint4*)(Qg + (size_t)(q0 + r)*64 + c);
        uint4 v0 = src[0], v1 = src[1], v2 = src[2], v3 = src[3];
        uint4* d = (uint4*)&sQ[r][c];
        d[0] = v0; d[1] = v1; d[2] = v2; d[3] = v3;
    }

    int kvr = tid >> 2, kvc = (tid & 3)*16;
    uint4 pk0, pk1, pv0, pv1;
    {
        pk0 = *(const uint4*)(Kg + (size_t)kvr*64 + kvc);
        pk1 = *(const uint4*)(Kg + (size_t)kvr*64 + kvc + 8);
        pv0 = *(const uint4*)(Vg + (size_t)kvr*64 + kvc);
        pv1 = *(const uint4*)(Vg + (size_t)kvr*64 + kvc + 8);
    }
    __syncthreads();

    uint32_t aq[4][4];
    {
        int r = wid*16 + (lane & 15);
        int cb = (lane >> 4)*8;
        #pragma unroll
        for (int kc = 0; kc < 4; kc++)
            ldsm_x4(aq[kc], smem_u32(&sQ[r][kc*16 + cb]));
    }

    int b_r2 = ((lane >> 4) << 3) + (lane & 7);
    int b_k2 = ((lane >> 3) & 1)*8;
    int v_r  = lane & 15;
    int v_c2 = ((lane >> 4) << 3);

    float lsum[2] = {0.f, 0.f};
    float oacc[8][4];
    #pragma unroll
    for (int nf = 0; nf < 8; nf++)
        #pragma unroll
        for (int q = 0; q < 4; q++) oacc[nf][q] = 0.f;

    for (int t = 0; t < SEQL/64; t++) {
        *(uint4*)&sK[kvr][kvc]     = pk0;
        *(uint4*)&sK[kvr][kvc + 8] = pk1;
        *(uint4*)&sV[kvr][kvc]     = pv0;
        *(uint4*)&sV[kvr][kvc + 8] = pv1;
        __syncthreads();
        if (t + 1 < SEQL/64) {
            const __nv_bfloat16* Kt = Kg + (size_t)(t+1)*64*64;
            const __nv_bfloat16* Vt = Vg + (size_t)(t+1)*64*64;
            pk0 = *(const uint4*)(Kt + (size_t)kvr*64 + kvc);
            pk1 = *(const uint4*)(Kt + (size_t)kvr*64 + kvc + 8);
            pv0 = *(const uint4*)(Vt + (size_t)kvr*64 + kvc);
            pv1 = *(const uint4*)(Vt + (size_t)kvr*64 + kvc + 8);
        }

        float s[8][4];
        #pragma unroll
        for (int nf = 0; nf < 8; nf++)
            #pragma unroll
            for (int q = 0; q < 4; q++) s[nf][q] = 0.f;
        #pragma unroll
        for (int kc = 0; kc < 4; kc++) {
            uint32_t bk[8][2];
            #pragma unroll
            for (int ntp = 0; ntp < 4; ntp++) {
                uint32_t b4[4];
                ldsm_x4(b4, smem_u32(&sK[ntp*16 + b_r2][kc*16 + b_k2]));
                bk[2*ntp][0]   = b4[0]; bk[2*ntp][1]   = b4[1];
                bk[2*ntp+1][0] = b4[2]; bk[2*ntp+1][1] = b4[3];
            }
            #pragma unroll
            for (int nf = 0; nf < 8; nf++)
                mma16816(s[nf], aq[kc], bk[nf]);
        }

        // fixed-shift softmax numerator; per-lane partial sums
        uint32_t pf[4][4];
        #pragma unroll
        for (int nf = 0; nf < 8; nf++) {
            float p0 = exp2f(s[nf][0] - SHIFT_);
            float p1 = exp2f(s[nf][1] - SHIFT_);
            float p2 = exp2f(s[nf][2] - SHIFT_);
            float p3 = exp2f(s[nf][3] - SHIFT_);
            lsum[0] += p0 + p1;
            lsum[1] += p2 + p3;
            s[nf][0] = p0; s[nf][1] = p1; s[nf][2] = p2; s[nf][3] = p3;
        }
        #pragma unroll
        for (int kc = 0; kc < 4; kc++) {
            pf[kc][0] = packbf(s[2*kc][0],   s[2*kc][1]);
            pf[kc][1] = packbf(s[2*kc][2],   s[2*kc][3]);
            pf[kc][2] = packbf(s[2*kc+1][0], s[2*kc+1][1]);
            pf[kc][3] = packbf(s[2*kc+1][2], s[2*kc+1][3]);
        }

        #pragma unroll
        for (int kc = 0; kc < 4; kc++) {
            uint32_t bv[8][2];
            #pragma unroll
            for (int nfp = 0; nfp < 4; nfp++) {
                uint32_t b4[4];
                ldsm_x4t(b4, smem_u32(&sV[kc*16 + v_r][nfp*16 + v_c2]));
                bv[2*nfp][0]   = b4[0]; bv[2*nfp][1]   = b4[1];
                bv[2*nfp+1][0] = b4[2]; bv[2*nfp+1][1] = b4[3];
            }
            #pragma unroll
            for (int nf = 0; nf < 8; nf++)
                mma16816(oacc[nf], pf[kc], bv[nf]);
        }
        __syncthreads();
    }

    // single end-of-loop quad reduction of the row sums
    #pragma unroll
    for (int hh = 0; hh < 2; hh++) {
        lsum[hh] += __shfl_xor_sync(0xffffffffu, lsum[hh], 1);
        lsum[hh] += __shfl_xor_sync(0xffffffffu, lsum[hh], 2);
    }

    int r0 = wid*16 + (lane >> 2);
    #pragma unroll
    for (int hh = 0; hh < 2; hh++) {
        float inv = 1.0f / lsum[hh];
        int row = q0 + r0 + hh*8;
        size_t o = ((size_t)(b*SEQL) + row)*DIM_ + h*64 + (lane & 3)*2;
        #pragma unroll
        for (int nf = 0; nf < 8; nf++) {
            __nv_bfloat162 p = __floats2bfloat162_rn(oacc[nf][hh*2]*inv, oacc[nf][hh*2+1]*inv);
            *(__nv_bfloat162*)(g_attnb + o + nf*8) = p;
        }
    }
}

// ------------- combine (H in bf16; optional fused patch-gather output) -------
__device__ __forceinline__ float block_sum(float v, float* shm)
{
    #pragma unroll
    for (int o = 16; o; o >>= 1) v += __shfl_xor_sync(0xffffffffu, v, o);
    __syncthreads();
    if ((threadIdx.x & 31) == 0) shm[threadIdx.x >> 5] = v;
    __syncthreads();
    if (threadIdx.x < 32) {
        float t = (threadIdx.x < 8) ? shm[threadIdx.x] : 0.f;
        #pragma unroll
        for (int o = 4; o; o >>= 1) t += __shfl_xor_sync(0xffffffffu, t, o);
        if (threadIdx.x == 0) shm[0] = t;
    }
    __syncthreads();
    return shm[0];
}

__global__ __launch_bounds__(256) void combine_kernel(const float* __restrict__ X,
                                                      const __nv_bfloat16* __restrict__ H,
                                                      const float* __restrict__ alpha,
                                                      float* __restrict__ Out,
                                                      __nv_bfloat16* __restrict__ Xp)
{
    __shared__ float shm[8];
    int row = blockIdx.x;
    const float* xp = X + (size_t)row*DIM_;
    const __nv_bfloat16* hp = H + (size_t)row*DIM_;
    float xv[4], hv[4];
    float sx = 0.f, sh = 0.f;
    #pragma unroll
    for (int i = 0; i < 4; i++) {
        int j = threadIdx.x + i*256;
        xv[i] = xp[j]; hv[i] = __bfloat162float(hp[j]);
        sx = fmaf(xv[i], xv[i], sx);
        sh = fmaf(hv[i], hv[i], sh);
    }
    float nx = block_sum(sx, shm);
    float nh = block_sum(sh, shm);
    float invx = 1.0f / fmaxf(sqrtf(nx), 1e-12f);
    float invh = 1.0f / fmaxf(sqrtf(nh), 1e-12f);
    float yv[4]; float sy = 0.f;
    #pragma unroll
    for (int i = 0; i < 4; i++) {
        int j = threadIdx.x + i*256;
        float lr = fabsf(alpha[j] * 1.6f);
        float hn = xv[i]*invx;
        float y = hn + lr*(hv[i]*invh - hn);
        yv[i] = y; sy = fmaf(y, y, sy);
    }
    float ny = block_sum(sy, shm);
    float invy = 1.0f / fmaxf(sqrtf(ny), 1e-12f);
    int bb = row >> 11, ss = row & (SEQL-1);
    int ib = ss >> 4, rr = ss & 15;
    #pragma unroll
    for (int i = 0; i < 4; i++) {
        int j = threadIdx.x + i*256;
        float y = yv[i]*invy;
        Out[(size_t)row*DIM_ + j] = y;
        if (Xp) {
            int p = ib*64 + (j >> 4);
            Xp[((size_t)(bb*NPATB + p))*256 + rr*16 + (j & 15)] = __float2bfloat16(y);
        }
    }
}

// ------------------------------- launcher -------------------------------------
extern "C" void kernel_launch(void* const* d_in, const int* in_sizes, int n_in,
                              void* d_out, int out_size)
{
    const float* x   = (const float*)d_in[0];
    const float* fc  = (const float*)d_in[1];
    const float* fs  = (const float*)d_in[2];
    const float* ada = (const float*)d_in[3];
    const float* wq  = (const float*)d_in[4];
    const float* wk  = (const float*)d_in[5];
    const float* wv  = (const float*)d_in[6];
    const float* wo  = (const float*)d_in[7];
    const float* sqk = (const float*)d_in[8];
    const float* w1  = (const float*)d_in[9];
    const float* w2  = (const float*)d_in[10];
    const float* w3  = (const float*)d_in[11];
    const float* su  = (const float*)d_in[12];
    const float* sv  = (const float*)d_in[13];
    const float* pw  = (const float*)d_in[14];
    const float* pb  = (const float*)d_in[15];
    const float* aat = (const float*)d_in[16];
    const float* aml = (const float*)d_in[17];
    float* out = (float*)d_out;

    float *x1;
    __nv_bfloat16 *xmodb, *attnb, *x1mb, *hhb, *qkvb, *kmat, *xpat, *hab, *hmb;
    __nv_bfloat16 *wqkvt, *wot, *w13t, *w2t;
    cudaGetSymbolAddress((void**)&x1,   g_x1);
    cudaGetSymbolAddress((void**)&xmodb, g_xmodb);
    cudaGetSymbolAddress((void**)&attnb, g_attnb);
    cudaGetSymbolAddress((void**)&x1mb,  g_x1mb);
    cudaGetSymbolAddress((void**)&hhb,   g_hhb);
    cudaGetSymbolAddress((void**)&qkvb,  g_qkvb);
    cudaGetSymbolAddress((void**)&kmat,  g_kmat);
    cudaGetSymbolAddress((void**)&xpat,  g_xpat);
    cudaGetSymbolAddress((void**)&hab,   g_hab);
    cudaGetSymbolAddress((void**)&hmb,   g_hmb);
    cudaGetSymbolAddress((void**)&wqkvt, g_wqkvt);
    cudaGetSymbolAddress((void**)&wot,   g_wot);
    cudaGetSymbolAddress((void**)&w13t,  g_w13t);
    cudaGetSymbolAddress((void**)&w2t,   g_w2t);

    cudaFuncSetAttribute(tgemm_epi<EpiBF16>,   cudaFuncAttributeMaxDynamicSharedMemorySize, GEMM_SMEM);
    cudaFuncSetAttribute(tgemm_epi<EpiSwiglu>, cudaFuncAttributeMaxDynamicSharedMemorySize, GEMM_SMEM);
    cudaFuncSetAttribute(tgemm_mod,            cudaFuncAttributeMaxDynamicSharedMemorySize, GEMM_SMEM);

    // 0. weight transposes (bf16, [N][K]); qkv packed; w1/w3 interleaved
    wtrans_kernel<<<dim3(DIM_/32, DIM_/32), dim3(32,8)>>>(wq, wqkvt,               DIM_, DIM_, 1, 0);
    wtrans_kernel<<<dim3(DIM_/32, DIM_/32), dim3(32,8)>>>(wk, wqkvt + DIM_*DIM_,   DIM_, DIM_, 1, 0);
    wtrans_kernel<<<dim3(DIM_/32, DIM_/32), dim3(32,8)>>>(wv, wqkvt + 2*DIM_*DIM_, DIM_, DIM_, 1, 0);
    wtrans_kernel<<<dim3(DIM_/32, DIM_/32), dim3(32,8)>>>(wo, wot, DIM_, DIM_, 1, 0);
    wtrans_kernel<<<dim3(HID_/32, DIM_/32), dim3(32,8)>>>(w1, w13t, DIM_, HID_, 2, 0);
    wtrans_kernel<<<dim3(HID_/32, DIM_/32), dim3(32,8)>>>(w3, w13t, DIM_, HID_, 2, 1);
    wtrans_kernel<<<dim3(DIM_/32, HID_/32), dim3(32,8)>>>(w2, w2t, HID_, DIM_, 1, 0);

    // 1. adafm projection + conv kernel matrices
    proj_kernel<<<dim3(2, 2), 256>>>(ada, pw, pb);
    kconv_kernel<<<dim3(2, 2), 256>>>();
    kmat_kernel<<<4, 256>>>();

    // 2. attention branch
    gather_kernel<<<dim3(NPATB/4, B_), 256>>>(x, xpat);
    tgemm_mod<<<dim3(2, NPATB/256, B_), 256, GEMM_SMEM>>>(xpat, kmat, xmodb);
    tgemm_epi<EpiBF16><<<dim3(NQKV/128, NTOK/256), 256, GEMM_SMEM>>>(xmodb, wqkvt, DIM_, EpiBF16{qkvb, NQKV});
    rotnorm_kernel<<<NTOK, 512>>>(fc, fs, sqk);
    attn_kernel<<<dim3(SEQL/128, NH_, B_), 256>>>();
    tgemm_epi<EpiBF16><<<dim3(DIM_/128, NTOK/256), 256, GEMM_SMEM>>>(attnb, wot, DIM_, EpiBF16{hab, DIM_});
    combine_kernel<<<NTOK, 256>>>(x, hab, aat, x1, xpat);   // fused gather for MLP branch

    // 3. mlp branch
    tgemm_mod<<<dim3(2, NPATB/256, B_), 256, GEMM_SMEM>>>(xpat, kmat + 2*256*256, x1mb);
    tgemm_epi<EpiSwiglu><<<dim3(N13/128, NTOK/256), 256, GEMM_SMEM>>>(x1mb, w13t, DIM_, EpiSwiglu{hhb, su, sv});
    tgemm_epi<EpiBF16><<<dim3(DIM_/128, NTOK/256), 256, GEMM_SMEM>>>(hhb, w2t, HID_, EpiBF16{hmb, DIM_});
    combine_kernel<<<NTOK, 256>>>(x1, hmb, aml, out, nullptr);
}